// round 1
// baseline (speedup 1.0000x reference)
#include <cuda_runtime.h>

// BKT_RNN: B=8192 rows, T=2048 sequential steps, H=4, X=1.
// One thread per batch row; weights register-resident; 8-step chunks for
// full-sector (32B) coalesced-per-thread global I/O.

#define TT 2048
#define BB 8192

__device__ double g_loss_acc;

__global__ void k_zero() { g_loss_acc = 0.0; }

__device__ __forceinline__ float ex2f(float v) {
    float r; asm("ex2.approx.f32 %0, %1;" : "=f"(r) : "f"(v)); return r;
}
__device__ __forceinline__ float rcpf(float v) {
    float r; asm("rcp.approx.f32 %0, %1;" : "=f"(r) : "f"(v)); return r;
}
__device__ __forceinline__ float lg2f(float v) {
    float r; asm("lg2.approx.f32 %0, %1;" : "=f"(r) : "f"(v)); return r;
}

__global__ void __launch_bounds__(32) k_bkt(
    const float* __restrict__ x,   const float* __restrict__ y,
    const float* __restrict__ Wxh, const float* __restrict__ Whh,
    const float* __restrict__ bh,  const float* __restrict__ Wy,
    const float* __restrict__ by,  const float* __restrict__ prior,
    float* __restrict__ corrects,  float* __restrict__ latents)
{
    const int b = blockIdx.x * 32 + threadIdx.x;

    // Pre-scale all weights by -log2(e): sigmoid(z) = rcp(1 + ex2(-z*log2e)).
    const float NL2E = -1.4426950408889634f;
    float A[4][4], av[4];      // scaled Wy, by   (p-head)
    float Wh[4][4], bhv[4];    // scaled Whh, bh  (h recurrence)
    float wx[4];               // scaled Wxh
    #pragma unroll
    for (int j = 0; j < 4; j++) {
        av[j]  = NL2E * __ldg(by  + j);
        bhv[j] = NL2E * __ldg(bh  + j);
        wx[j]  = NL2E * __ldg(Wxh + j);
        #pragma unroll
        for (int i = 0; i < 4; i++) {
            A[i][j]  = NL2E * __ldg(Wy  + i * 4 + j);
            Wh[i][j] = NL2E * __ldg(Whh + i * 4 + j);
        }
    }

    float h0 = 0.f, h1 = 0.f, h2 = 0.f, h3 = 0.f;
    float lat  = __ldg(prior);
    float lsum = 0.f;

    const float4* xp = (const float4*)(x + (size_t)b * TT);
    const float4* yp = (const float4*)(y + (size_t)b * TT);
    float4* cp = (float4*)(corrects + (size_t)b * TT);
    float4* lp = (float4*)(latents  + (size_t)b * TT);

    for (int t4 = 0; t4 < TT / 4; t4 += 2) {
        float4 xa = xp[t4], xb = xp[t4 + 1];
        float4 ya = yp[t4], yb = yp[t4 + 1];
        float xv[8] = {xa.x, xa.y, xa.z, xa.w, xb.x, xb.y, xb.z, xb.w};
        float yv[8] = {ya.x, ya.y, ya.z, ya.w, yb.x, yb.y, yb.z, yb.w};
        float cb[8], lb[8];

        #pragma unroll
        for (int k = 0; k < 8; k++) {
            // p = sigmoid(h @ Wy + by) with pre-scaled weights
            float p[4];
            #pragma unroll
            for (int j = 0; j < 4; j++) {
                float z = av[j];
                z = fmaf(h0, A[0][j], z);
                z = fmaf(h1, A[1][j], z);
                z = fmaf(h2, A[2][j], z);
                z = fmaf(h3, A[3][j], z);
                p[j] = rcpf(1.f + ex2f(z));
            }
            const float l_ = p[0], f_ = p[1], g_ = p[2], s_ = p[3];

            // BKT latent update. k_t1*correct == lat*(1-s) exactly -> 1 rcp only.
            const float oml     = 1.f - lat;
            const float a       = lat * (1.f - s_);
            const float correct = fmaf(oml, g_, a);
            const float ls      = lat * s_;
            const float den0    = fmaf(oml, 1.f - g_, ls);
            const float k0      = ls * rcpf(den0);
            const float m       = fmaf(k0, 1.f - correct, a);
            lat = fmaf(m, 1.f - f_ - l_, l_);   // m*(1-f) + (1-m)*l

            // h_new = sigmoid(x_t*Wxh + h@Whh + bh)  (uses OLD h)
            const float xt = xv[k];
            float n0 = fmaf(xt, wx[0], bhv[0]);
            float n1 = fmaf(xt, wx[1], bhv[1]);
            float n2 = fmaf(xt, wx[2], bhv[2]);
            float n3 = fmaf(xt, wx[3], bhv[3]);
            n0 = fmaf(h0, Wh[0][0], n0); n1 = fmaf(h0, Wh[0][1], n1);
            n2 = fmaf(h0, Wh[0][2], n2); n3 = fmaf(h0, Wh[0][3], n3);
            n0 = fmaf(h1, Wh[1][0], n0); n1 = fmaf(h1, Wh[1][1], n1);
            n2 = fmaf(h1, Wh[1][2], n2); n3 = fmaf(h1, Wh[1][3], n3);
            n0 = fmaf(h2, Wh[2][0], n0); n1 = fmaf(h2, Wh[2][1], n1);
            n2 = fmaf(h2, Wh[2][2], n2); n3 = fmaf(h2, Wh[2][3], n3);
            n0 = fmaf(h3, Wh[3][0], n0); n1 = fmaf(h3, Wh[3][1], n1);
            n2 = fmaf(h3, Wh[3][2], n2); n3 = fmaf(h3, Wh[3][3], n3);
            h0 = rcpf(1.f + ex2f(n0));
            h1 = rcpf(1.f + ex2f(n1));
            h2 = rcpf(1.f + ex2f(n2));
            h3 = rcpf(1.f + ex2f(n3));

            // Loss contribution: y in {0,1} exactly -> single log.
            const float c   = fminf(fmaxf(correct, 1e-7f), 1.0f - 1e-7f);
            const float sel = (yv[k] != 0.f) ? c : (1.f - c);
            lsum += lg2f(sel);

            cb[k] = correct;
            lb[k] = lat;
        }

        cp[t4]     = make_float4(cb[0], cb[1], cb[2], cb[3]);
        cp[t4 + 1] = make_float4(cb[4], cb[5], cb[6], cb[7]);
        lp[t4]     = make_float4(lb[0], lb[1], lb[2], lb[3]);
        lp[t4 + 1] = make_float4(lb[4], lb[5], lb[6], lb[7]);
    }

    // Warp reduce + one double atomic per warp.
    #pragma unroll
    for (int o = 16; o > 0; o >>= 1)
        lsum += __shfl_xor_sync(0xffffffffu, lsum, o);
    if ((threadIdx.x & 31) == 0)
        atomicAdd(&g_loss_acc, (double)lsum);
}

__global__ void k_final(float* __restrict__ loss) {
    // loss = -mean(ln terms) = -ln2 * sum_log2 / (B*T)
    loss[0] = (float)(-0.6931471805599453 * g_loss_acc / ((double)BB * (double)TT));
}

extern "C" void kernel_launch(void* const* d_in, const int* in_sizes, int n_in,
                              void* d_out, int out_size) {
    const float* x     = (const float*)d_in[0];
    const float* y     = (const float*)d_in[1];
    const float* Wxh   = (const float*)d_in[2];
    const float* Whh   = (const float*)d_in[3];
    const float* bh    = (const float*)d_in[4];
    const float* Wy    = (const float*)d_in[5];
    const float* by    = (const float*)d_in[6];
    const float* prior = (const float*)d_in[7];

    float* corrects = (float*)d_out;
    float* latents  = (float*)d_out + (size_t)BB * TT;
    float* loss     = (float*)d_out + 2 * (size_t)BB * TT;

    k_zero<<<1, 1>>>();
    k_bkt<<<BB / 32, 32>>>(x, y, Wxh, Whh, bh, Wy, by, prior, corrects, latents);
    k_final<<<1, 1>>>(loss);
}